// round 16
// baseline (speedup 1.0000x reference)
#include <cuda_runtime.h>
#include <cuda_fp16.h>
#include <math.h>
#include <stdint.h>

#define Bb 16
#define Cc 256
#define CC2 512
#define Ll 8192
#define EPSV 1e-5f
#define TLI1 62
#define NT1 133              // ceil(8192/62)

// scratch
__device__ __half g_gate[Bb * Cc * Ll];   // fp16 gate
__device__ float g_pool[Bb * Cc];
__device__ float g_scale[Bb * Cc];
// weights pre-packed as mma.m16n8k16 A-fragments (fp16):
__device__ uint4 g_w1f[16384];   // MT=32 (M=512), 16 panels
__device__ uint4 g_w2f[8192];    // MT=16 (M=256), 16 panels

// ---------------- helpers ----------------
__device__ __forceinline__ uint32_t smem_u32(const void* p) {
    uint32_t a;
    asm("{ .reg .u64 t; cvta.to.shared.u64 t, %1; cvt.u32.u64 %0, t; }" : "=r"(a) : "l"(p));
    return a;
}
__device__ __forceinline__ void ldsm4(uint32_t* r, uint32_t addr) {
    asm volatile("ldmatrix.sync.aligned.m8n8.x4.shared.b16 {%0,%1,%2,%3}, [%4];"
        : "=r"(r[0]), "=r"(r[1]), "=r"(r[2]), "=r"(r[3]) : "r"(addr));
}
__device__ __forceinline__ void mma16816(float* c, const uint32_t* a, const uint32_t* b) {
    asm volatile("mma.sync.aligned.m16n8k16.row.col.f32.f16.f16.f32 "
        "{%0,%1,%2,%3}, {%4,%5,%6,%7}, {%8,%9}, {%0,%1,%2,%3};"
        : "+f"(c[0]), "+f"(c[1]), "+f"(c[2]), "+f"(c[3])
        : "r"(a[0]), "r"(a[1]), "r"(a[2]), "r"(a[3]), "r"(b[0]), "r"(b[1]));
}
__device__ __forceinline__ uint32_t pack_hi2f(float v0, float v1, uint32_t* lo) {
    __half h0 = __float2half_rn(v0);
    __half h1 = __float2half_rn(v1);
    __half l0 = __float2half_rn(v0 - __half2float(h0));
    __half l1 = __float2half_rn(v1 - __half2float(h1));
    __half2 hp = __halves2half2(h0, h1);
    __half2 lp = __halves2half2(l0, l1);
    *lo = *reinterpret_cast<uint32_t*>(&lp);
    return *reinterpret_cast<uint32_t*>(&hp);
}
__device__ __forceinline__ uint32_t pack2f(float v0, float v1) {
    __half2 hp = __halves2half2(__float2half_rn(v0), __float2half_rn(v1));
    return *reinterpret_cast<uint32_t*>(&hp);
}
// B-tile byte offset: row l (n dim), channel c (k dim), swizzled for ldmatrix.
__device__ __forceinline__ uint32_t bswz(int l, int c) {
    return (uint32_t)(l * 512 + ((((c >> 3) ^ (l & 7)) << 4) | ((c & 7) * 2)));
}

// ---------------------------------------------------------------------------
// K0: pack weights into fp16 mma A-fragment layout; zero g_pool
// ---------------------------------------------------------------------------
__global__ __launch_bounds__(256) void k0_split(const float* __restrict__ w1,
                                                const float* __restrict__ w2)
{
    int idx = blockIdx.x * 256 + threadIdx.x;
    if (idx < Bb * Cc) g_pool[idx] = 0.f;

    if (idx < 16384) {                 // w1 fragments: MT=32
        int p = idx >> 10, rem = idx & 1023;
        int mt = rem >> 5, lane = rem & 31;
        int r = mt * 16 + (lane >> 2);
        int c = p * 16 + (lane & 3) * 2;
        const float* A = w1;
        uint4 hi;
        hi.x = pack2f(A[r * Cc + c],           A[r * Cc + c + 1]);
        hi.y = pack2f(A[(r + 8) * Cc + c],     A[(r + 8) * Cc + c + 1]);
        hi.z = pack2f(A[r * Cc + c + 8],       A[r * Cc + c + 9]);
        hi.w = pack2f(A[(r + 8) * Cc + c + 8], A[(r + 8) * Cc + c + 9]);
        g_w1f[idx] = hi;
    } else if (idx < 24576) {          // w2 fragments: MT=16
        int i2 = idx - 16384;
        int p = i2 >> 9, rem = i2 & 511;
        int mt = rem >> 5, lane = rem & 31;
        int r = mt * 16 + (lane >> 2);
        int c = p * 16 + (lane & 3) * 2;
        const float* A = w2;
        uint4 hi;
        hi.x = pack2f(A[r * Cc + c],           A[r * Cc + c + 1]);
        hi.y = pack2f(A[(r + 8) * Cc + c],     A[(r + 8) * Cc + c + 1]);
        hi.z = pack2f(A[r * Cc + c + 8],       A[r * Cc + c + 9]);
        hi.w = pack2f(A[(r + 8) * Cc + c + 8], A[(r + 8) * Cc + c + 9]);
        g_w2f[i2] = hi;
    }
}

// ---------------------------------------------------------------------------
// K1: LN + pw1 (M=512, N=64, fp16 2-term) + register dwconv + gate + pool
// 512 threads, 16 warps; warp w owns m-tiles {w, w+16} (gate pairing).
// smem: B hi [0,32K) lo [32K,64K); red2 [64K,+4K) (redm alias); stat [+4K,+512)
// ---------------------------------------------------------------------------
#define K1_B    0
#define K1_RED  65536
#define K1_STAT 69632
#define K1_SMEM 70144

__global__ __launch_bounds__(512, 1) void k1_ln_pw1(
    const float* __restrict__ x, const float* __restrict__ gamma,
    const float* __restrict__ beta, const float* __restrict__ b1,
    const float* __restrict__ wd, const float* __restrict__ bd_)
{
    extern __shared__ char sm[];
    float* red2 = (float*)(sm + K1_RED);
    float* stat = (float*)(sm + K1_STAT);
    const uint32_t smb = smem_u32(sm);
    const int b    = blockIdx.y;
    const int tile = blockIdx.x;
    const int l0   = tile * TLI1 - 1;   // global l of local col 0
    const int tid  = threadIdx.x;
    const int w    = tid >> 5, lane = tid & 31;

    // ---- LN stats: 64 columns. warp w: half=w>>3, wi=w&7; col=half*32+lane;
    //      sums channels {wi, wi+8, ..., wi+248} ----
    {
        const int half = w >> 3, wi = w & 7;
        int lg = l0 + half * 32 + lane;
        bool ok = (lg >= 0 && lg < Ll);
        float s = 0.f, sq = 0.f;
        if (ok) {
            const float* xp = x + (size_t)(b * Cc + wi) * Ll + lg;
            for (int c = 0; c < 32; c++) {
                float v = __ldg(xp + (size_t)c * 8 * Ll);
                s += v; sq += v * v;
            }
        }
        red2[half * 256 + wi * 32 + lane]       = s;
        red2[512 + half * 256 + wi * 32 + lane] = sq;
    }
    __syncthreads();
    if (tid < 64) {
        int half = tid >> 5, ln = tid & 31;
        int base = half * 256 + ln;
        float s = 0.f, sq = 0.f;
        #pragma unroll
        for (int k = 0; k < 8; k++) { s += red2[base + k * 32]; sq += red2[512 + base + k * 32]; }
        float mu = s * (1.f / Cc);
        float var = sq * (1.f / Cc) - mu * mu;
        stat[tid]      = mu;
        stat[64 + tid] = rsqrtf(var + EPSV);
    }
    __syncthreads();

    // ---- normalize (2nd x read, cache hit) + fp16 split -> B [64 l][256 c]
    for (int i = tid; i < 128 * 64; i += 512) {
        int cp = i >> 6, l = i & 63;
        int c = cp * 2;
        int lg = l0 + l;
        bool ok = (lg >= 0 && lg < Ll);
        float x0 = ok ? __ldg(&x[(size_t)(b * Cc + c) * Ll + lg]) : 0.f;
        float x1 = ok ? __ldg(&x[(size_t)(b * Cc + c + 1) * Ll + lg]) : 0.f;
        float mu = stat[l], rs = stat[64 + l];
        float v0 = (x0 - mu) * rs * __ldg(&gamma[c]) + __ldg(&beta[c]);
        float v1 = (x1 - mu) * rs * __ldg(&gamma[c + 1]) + __ldg(&beta[c + 1]);
        uint32_t lop;
        uint32_t hip = pack_hi2f(v0, v1, &lop);
        uint32_t by = bswz(l, c);
        *(uint32_t*)(sm + K1_B + by)         = hip;
        *(uint32_t*)(sm + K1_B + 32768 + by) = lop;
    }
    __syncthreads();

    // ---- GEMM: M=512, N=64, K=256. warp w owns mt {w, w+16} ----
    const int lr  = lane & 7;
    const int gb0 = (lane >> 3) & 1;
    const int gb1 = lane >> 4;
    uint32_t bBase[4];
    #pragma unroll
    for (int bp = 0; bp < 4; bp++)
        bBase[bp] = smb + K1_B + (uint32_t)((bp * 16 + gb1 * 8 + lr) * 512);

    float acc[2][8][4];
    #pragma unroll
    for (int mt = 0; mt < 2; mt++)
        #pragma unroll
        for (int nt = 0; nt < 8; nt++)
            #pragma unroll
            for (int q = 0; q < 4; q++) acc[mt][nt][q] = 0.f;

    const uint4* A0H = g_w1f + w * 32 + lane;           // mt = w     (rows m)
    const uint4* A1H = g_w1f + (16 + w) * 32 + lane;    // mt = w+16  (rows m+256)

    #pragma unroll 2
    for (int p = 0; p < 16; ++p) {
        uint32_t kx = (uint32_t)(((p * 2 + gb0) ^ lr) << 4);
        uint32_t Bh[16], Bl[16];
        #pragma unroll
        for (int bp = 0; bp < 4; bp++) {
            ldsm4(&Bh[bp * 4], bBase[bp] + kx);
            ldsm4(&Bl[bp * 4], bBase[bp] + 32768 + kx);
        }
        uint4 a0h = __ldg(A0H + p * 1024);
        uint4 a1h = __ldg(A1H + p * 1024);
        #pragma unroll
        for (int nt = 0; nt < 8; nt++) {
            mma16816(acc[0][nt], (const uint32_t*)&a0h, &Bh[nt * 2]);
            mma16816(acc[0][nt], (const uint32_t*)&a0h, &Bl[nt * 2]);
            mma16816(acc[1][nt], (const uint32_t*)&a1h, &Bh[nt * 2]);
            mma16816(acc[1][nt], (const uint32_t*)&a1h, &Bl[nt * 2]);
        }
    }

    // ---- register epilogue: bias + dwconv (quad shfl halo) + gate + pool ----
    float* redm = red2;                 // alias (LN reductions dead)
    const int j  = lane & 3;
    const int rl = lane >> 2;
    const int srcL = (lane & ~3) | ((j + 3) & 3);
    const int srcR = (lane & ~3) | ((j + 1) & 3);

    #pragma unroll
    for (int q = 0; q < 2; ++q) {
        const int m  = w * 16 + q * 8 + rl;     // rows 0..255
        const int m2 = m + Cc;                  // rows 256..511
        const float biA = __ldg(&b1[m]);
        const float biB = __ldg(&b1[m2]);
        float zA0[8], zA1[8], zB0[8], zB1[8];
        #pragma unroll
        for (int nt = 0; nt < 8; nt++) {
            zA0[nt] = acc[0][nt][q * 2]     + biA;
            zA1[nt] = acc[0][nt][q * 2 + 1] + biA;
            zB0[nt] = acc[1][nt][q * 2]     + biB;
            zB1[nt] = acc[1][nt][q * 2 + 1] + biB;
        }
        float rA1[8], rA0[8], rB1[8], rB0[8];
        #pragma unroll
        for (int nt = 0; nt < 8; nt++) {
            rA1[nt] = __shfl_sync(0xFFFFFFFFu, zA1[nt], srcL);
            rA0[nt] = __shfl_sync(0xFFFFFFFFu, zA0[nt], srcR);
            rB1[nt] = __shfl_sync(0xFFFFFFFFu, zB1[nt], srcL);
            rB0[nt] = __shfl_sync(0xFFFFFFFFu, zB0[nt], srcR);
        }
        const float wa0 = __ldg(&wd[m * 3 + 0]),  wa1 = __ldg(&wd[m * 3 + 1]),
                    wa2 = __ldg(&wd[m * 3 + 2]),  ba  = __ldg(&bd_[m]);
        const float wb0 = __ldg(&wd[m2 * 3 + 0]), wb1 = __ldg(&wd[m2 * 3 + 1]),
                    wb2 = __ldg(&wd[m2 * 3 + 2]), bb  = __ldg(&bd_[m2]);
        __half* orow = g_gate + (size_t)(b * Cc + m) * Ll;
        float psum = 0.f;
        #pragma unroll
        for (int nt = 0; nt < 8; nt++) {
            #pragma unroll
            for (int e = 0; e < 2; e++) {
                int co = nt * 8 + 2 * j + e;
                if (co >= 1 && co <= 62) {
                    int lg = l0 + co;
                    if (lg >= 0 && lg < Ll) {
                        float am1, ac, ap1, bm1, bc, bp1;
                        if (e == 0) {
                            am1 = (j == 0) ? (nt > 0 ? rA1[nt - 1] : 0.f) : rA1[nt];
                            bm1 = (j == 0) ? (nt > 0 ? rB1[nt - 1] : 0.f) : rB1[nt];
                            ac = zA0[nt]; ap1 = zA1[nt];
                            bc = zB0[nt]; bp1 = zB1[nt];
                        } else {
                            am1 = zA0[nt]; ac = zA1[nt];
                            bm1 = zB0[nt]; bc = zB1[nt];
                            ap1 = (j == 3) ? (nt < 7 ? rA0[nt + 1] : 0.f) : rA0[nt];
                            bp1 = (j == 3) ? (nt < 7 ? rB0[nt + 1] : 0.f) : rB0[nt];
                        }
                        if (lg - 1 < 0)   { am1 = 0.f; bm1 = 0.f; }
                        if (lg + 1 >= Ll) { ap1 = 0.f; bp1 = 0.f; }
                        float d1 = wa0 * am1 + wa1 * ac + wa2 * ap1 + ba;
                        float d2 = wb0 * bm1 + wb1 * bc + wb2 * bp1 + bb;
                        float g = d1 * d2;
                        orow[lg] = __float2half_rn(g);
                        psum += g;
                    }
                }
            }
        }
        psum += __shfl_xor_sync(0xFFFFFFFFu, psum, 1);
        psum += __shfl_xor_sync(0xFFFFFFFFu, psum, 2);
        if (j == 0) redm[m] = psum;
    }
    __syncthreads();
    if (tid < 256) {
        float v = redm[tid];
        if (v != 0.f) atomicAdd(&g_pool[b * Cc + tid], v * (1.f / Ll));
    }
}

// ---------------------------------------------------------------------------
// K3: SCA scale = sigmoid(ws @ pool + bs); one warp per output
// ---------------------------------------------------------------------------
__global__ __launch_bounds__(256) void k3_scale(
    const float* __restrict__ ws, const float* __restrict__ bs)
{
    __shared__ float sp[Cc];
    const int b = blockIdx.x;
    const int w = threadIdx.x >> 5, lane = threadIdx.x & 31;
    const int c = blockIdx.y * 8 + w;
    sp[threadIdx.x] = g_pool[b * Cc + threadIdx.x];
    __syncthreads();
    const float4* wr = (const float4*)(ws + c * Cc);
    const float4* pp = (const float4*)sp;
    float4 a0 = __ldg(&wr[lane * 2]), a1 = __ldg(&wr[lane * 2 + 1]);
    float4 p0 = pp[lane * 2], p1 = pp[lane * 2 + 1];
    float s = a0.x * p0.x + a0.y * p0.y + a0.z * p0.z + a0.w * p0.w
            + a1.x * p1.x + a1.y * p1.y + a1.z * p1.z + a1.w * p1.w;
    #pragma unroll
    for (int o = 16; o; o >>= 1) s += __shfl_xor_sync(0xFFFFFFFFu, s, o);
    if (lane == 0)
        g_scale[b * Cc + c] = 1.f / (1.f + expf(-(s + __ldg(&bs[c]))));
}

// ---------------------------------------------------------------------------
// K4: pw2 (M=256, N=64, fp16 2-term) + bias + residual, register epilogue.
// 256 threads, 2 CTAs/SM. smem: B hi [0,32K) lo [32K,64K)  (unchanged R15)
// ---------------------------------------------------------------------------
#define K4_B 0
#define K4_SMEM 65536

__global__ __launch_bounds__(256, 2) void k4_pw2(
    const float* __restrict__ x, const float* __restrict__ b2,
    float* __restrict__ out)
{
    extern __shared__ char sm[];
    const uint32_t smb = smem_u32(sm);
    const int b = blockIdx.y, tile = blockIdx.x, tid = threadIdx.x;
    const int w = tid >> 5, lane = tid & 31;
    const int l0 = tile * 64;

    // ---- B tile: fp16 gate * scale -> fp16 split [64 l][256 c] ----
    for (int i = tid; i < 128 * 64; i += 256) {
        int cp = i >> 6, l = i & 63;
        int c = cp * 2;
        float g0 = __half2float(g_gate[(size_t)(b * Cc + c) * Ll + l0 + l]);
        float g1 = __half2float(g_gate[(size_t)(b * Cc + c + 1) * Ll + l0 + l]);
        float v0 = g0 * __ldg(&g_scale[b * Cc + c]);
        float v1 = g1 * __ldg(&g_scale[b * Cc + c + 1]);
        uint32_t lop;
        uint32_t hip = pack_hi2f(v0, v1, &lop);
        uint32_t by = bswz(l, c);
        *(uint32_t*)(sm + K4_B + by)         = hip;
        *(uint32_t*)(sm + K4_B + 32768 + by) = lop;
    }
    __syncthreads();

    const int lr  = lane & 7;
    const int gb0 = (lane >> 3) & 1;
    const int gb1 = lane >> 4;
    uint32_t bBase[4];
    #pragma unroll
    for (int bp = 0; bp < 4; bp++)
        bBase[bp] = smb + K4_B + (uint32_t)((bp * 16 + gb1 * 8 + lr) * 512);

    float acc[2][8][4];
    #pragma unroll
    for (int mt = 0; mt < 2; mt++)
        #pragma unroll
        for (int nt = 0; nt < 8; nt++)
            #pragma unroll
            for (int q = 0; q < 4; q++) acc[mt][nt][q] = 0.f;

    const uint4* A0H = g_w2f + w * 32 + lane;          // mt = w
    const uint4* A1H = g_w2f + (8 + w) * 32 + lane;    // mt = 8 + w

    #pragma unroll 2
    for (int p = 0; p < 16; ++p) {
        uint32_t kx = (uint32_t)(((p * 2 + gb0) ^ lr) << 4);
        uint32_t Bh[16], Bl[16];
        #pragma unroll
        for (int bp = 0; bp < 4; bp++) {
            ldsm4(&Bh[bp * 4], bBase[bp] + kx);
            ldsm4(&Bl[bp * 4], bBase[bp] + 32768 + kx);
        }
        uint4 a0h = __ldg(A0H + p * 512);
        uint4 a1h = __ldg(A1H + p * 512);
        #pragma unroll
        for (int nt = 0; nt < 8; nt++) {
            mma16816(acc[0][nt], (const uint32_t*)&a0h, &Bh[nt * 2]);
            mma16816(acc[0][nt], (const uint32_t*)&a0h, &Bl[nt * 2]);
            mma16816(acc[1][nt], (const uint32_t*)&a1h, &Bh[nt * 2]);
            mma16816(acc[1][nt], (const uint32_t*)&a1h, &Bl[nt * 2]);
        }
    }

    // ---- register epilogue: out = acc + b2 + x (float2 stores, 64 cols) ----
    const int j  = lane & 3;
    const int rl = lane >> 2;
    #pragma unroll
    for (int mt = 0; mt < 2; mt++) {
        const int r0 = (w + mt * 8) * 16 + rl;
        const float bi0 = __ldg(&b2[r0]);
        const float bi1 = __ldg(&b2[r0 + 8]);
        const float* xr0 = x + (size_t)(b * Cc + r0) * Ll + l0;
        const float* xr1 = xr0 + 8 * Ll;
        float* or0 = out + (size_t)(b * Cc + r0) * Ll + l0;
        float* or1 = or0 + 8 * Ll;
        #pragma unroll
        for (int nt = 0; nt < 8; nt++) {
            int co = nt * 8 + 2 * j;
            float2 x0 = *(const float2*)(xr0 + co);
            float2 x1 = *(const float2*)(xr1 + co);
            float2 o0, o1;
            o0.x = acc[mt][nt][0] + bi0 + x0.x;
            o0.y = acc[mt][nt][1] + bi0 + x0.y;
            o1.x = acc[mt][nt][2] + bi1 + x1.x;
            o1.y = acc[mt][nt][3] + bi1 + x1.y;
            *(float2*)(or0 + co) = o0;
            *(float2*)(or1 + co) = o1;
        }
    }
}

// ---------------------------------------------------------------------------
extern "C" void kernel_launch(void* const* d_in, const int* in_sizes, int n_in,
                              void* d_out, int out_size)
{
    const float* x     = (const float*)d_in[0];
    const float* gamma = (const float*)d_in[1];
    const float* beta  = (const float*)d_in[2];
    const float* w1    = (const float*)d_in[3];
    const float* b1    = (const float*)d_in[4];
    const float* wd    = (const float*)d_in[5];
    const float* bd    = (const float*)d_in[6];
    const float* wsm   = (const float*)d_in[7];
    const float* bs    = (const float*)d_in[8];
    const float* w2    = (const float*)d_in[9];
    const float* b2    = (const float*)d_in[10];
    float* out = (float*)d_out;

    // both >48KB dynamic smem: attributes REQUIRED (lesson from R12)
    cudaFuncSetAttribute(k1_ln_pw1, cudaFuncAttributeMaxDynamicSharedMemorySize, K1_SMEM);
    cudaFuncSetAttribute(k4_pw2,    cudaFuncAttributeMaxDynamicSharedMemorySize, K4_SMEM);

    k0_split<<<96, 256>>>(w1, w2);
    dim3 g1(NT1, Bb);
    k1_ln_pw1<<<g1, 512, K1_SMEM>>>(x, gamma, beta, b1, wd, bd);
    dim3 g3(Bb, 32);
    k3_scale<<<g3, 256>>>(wsm, bs);
    dim3 g4(Ll / 64, Bb);
    k4_pw2<<<g4, 256, K4_SMEM>>>(x, b2, out);
}

// round 17
// speedup vs baseline: 1.1299x; 1.1299x over previous
#include <cuda_runtime.h>
#include <cuda_fp16.h>
#include <math.h>
#include <stdint.h>

#define Bb 16
#define Cc 256
#define CC2 512
#define Ll 8192
#define EPSV 1e-5f
#define TLI1 30
#define NT1 274              // ceil(8192/30)

// scratch
__device__ __half g_gate[Bb * Cc * Ll];   // fp16 gate (exact B for k4)
__device__ float g_pool[Bb * Cc];
__device__ float g_scale[Bb * Cc];
// weights pre-packed as mma.m16n8k16 A-fragments (fp16):
__device__ uint4 g_w1f[16384];   // MT=32 (M=512), 16 panels
__device__ uint4 g_w2f[8192];    // MT=16 (M=256), 16 panels

// ---------------- helpers ----------------
__device__ __forceinline__ uint32_t smem_u32(const void* p) {
    uint32_t a;
    asm("{ .reg .u64 t; cvta.to.shared.u64 t, %1; cvt.u32.u64 %0, t; }" : "=r"(a) : "l"(p));
    return a;
}
__device__ __forceinline__ void ldsm4(uint32_t* r, uint32_t addr) {
    asm volatile("ldmatrix.sync.aligned.m8n8.x4.shared.b16 {%0,%1,%2,%3}, [%4];"
        : "=r"(r[0]), "=r"(r[1]), "=r"(r[2]), "=r"(r[3]) : "r"(addr));
}
__device__ __forceinline__ void mma16816(float* c, const uint32_t* a, const uint32_t* b) {
    asm volatile("mma.sync.aligned.m16n8k16.row.col.f32.f16.f16.f32 "
        "{%0,%1,%2,%3}, {%4,%5,%6,%7}, {%8,%9}, {%0,%1,%2,%3};"
        : "+f"(c[0]), "+f"(c[1]), "+f"(c[2]), "+f"(c[3])
        : "r"(a[0]), "r"(a[1]), "r"(a[2]), "r"(a[3]), "r"(b[0]), "r"(b[1]));
}
__device__ __forceinline__ uint32_t pack_hi2f(float v0, float v1, uint32_t* lo) {
    __half h0 = __float2half_rn(v0);
    __half h1 = __float2half_rn(v1);
    __half l0 = __float2half_rn(v0 - __half2float(h0));
    __half l1 = __float2half_rn(v1 - __half2float(h1));
    __half2 hp = __halves2half2(h0, h1);
    __half2 lp = __halves2half2(l0, l1);
    *lo = *reinterpret_cast<uint32_t*>(&lp);
    return *reinterpret_cast<uint32_t*>(&hp);
}
__device__ __forceinline__ uint32_t pack2f(float v0, float v1) {
    __half2 hp = __halves2half2(__float2half_rn(v0), __float2half_rn(v1));
    return *reinterpret_cast<uint32_t*>(&hp);
}
// scale a packed half2 by two fp32 scales (fp32 math, one final rounding)
__device__ __forceinline__ uint32_t h2scale(uint32_t h, float s0, float s1) {
    __half2 hv = *reinterpret_cast<__half2*>(&h);
    float2 f = __half22float2(hv);
    __half2 r = __floats2half2_rn(f.x * s0, f.y * s1);
    return *reinterpret_cast<uint32_t*>(&r);
}
// B-tile byte offset: row l (n dim), channel c (k dim), swizzled for ldmatrix.
__device__ __forceinline__ uint32_t bswz(int l, int c) {
    return (uint32_t)(l * 512 + ((((c >> 3) ^ (l & 7)) << 4) | ((c & 7) * 2)));
}

// ---------------------------------------------------------------------------
// K0: pack weights into fp16 mma A-fragment layout; zero g_pool
// ---------------------------------------------------------------------------
__global__ __launch_bounds__(256) void k0_split(const float* __restrict__ w1,
                                                const float* __restrict__ w2)
{
    int idx = blockIdx.x * 256 + threadIdx.x;
    if (idx < Bb * Cc) g_pool[idx] = 0.f;

    if (idx < 16384) {                 // w1 fragments: MT=32
        int p = idx >> 10, rem = idx & 1023;
        int mt = rem >> 5, lane = rem & 31;
        int r = mt * 16 + (lane >> 2);
        int c = p * 16 + (lane & 3) * 2;
        const float* A = w1;
        uint4 hi;
        hi.x = pack2f(A[r * Cc + c],           A[r * Cc + c + 1]);
        hi.y = pack2f(A[(r + 8) * Cc + c],     A[(r + 8) * Cc + c + 1]);
        hi.z = pack2f(A[r * Cc + c + 8],       A[r * Cc + c + 9]);
        hi.w = pack2f(A[(r + 8) * Cc + c + 8], A[(r + 8) * Cc + c + 9]);
        g_w1f[idx] = hi;
    } else if (idx < 24576) {          // w2 fragments: MT=16
        int i2 = idx - 16384;
        int p = i2 >> 9, rem = i2 & 511;
        int mt = rem >> 5, lane = rem & 31;
        int r = mt * 16 + (lane >> 2);
        int c = p * 16 + (lane & 3) * 2;
        const float* A = w2;
        uint4 hi;
        hi.x = pack2f(A[r * Cc + c],           A[r * Cc + c + 1]);
        hi.y = pack2f(A[(r + 8) * Cc + c],     A[(r + 8) * Cc + c + 1]);
        hi.z = pack2f(A[r * Cc + c + 8],       A[r * Cc + c + 9]);
        hi.w = pack2f(A[(r + 8) * Cc + c + 8], A[(r + 8) * Cc + c + 9]);
        g_w2f[i2] = hi;
    }
}

// ---------------------------------------------------------------------------
// K1: LN + pw1 (M=512, N=32, fp16 2-term) — R15 shape (proven), fp16 gate.
// 256 threads, 2 CTAs/SM. smem: B hi [0,16K) lo [16K,32K);
// red2 [32K,+2K) (redm alias); stat [34K,+256)
// ---------------------------------------------------------------------------
#define K1_B    0
#define K1_RED  32768
#define K1_STAT 34816
#define K1_SMEM 35072

__global__ __launch_bounds__(256, 2) void k1_ln_pw1(
    const float* __restrict__ x, const float* __restrict__ gamma,
    const float* __restrict__ beta, const float* __restrict__ b1,
    const float* __restrict__ wd, const float* __restrict__ bd_)
{
    extern __shared__ char sm[];
    float* red2 = (float*)(sm + K1_RED);
    float* stat = (float*)(sm + K1_STAT);
    const uint32_t smb = smem_u32(sm);
    const int b    = blockIdx.y;
    const int tile = blockIdx.x;
    const int l0   = tile * TLI1 - 1;
    const int tid  = threadIdx.x;
    const int w    = tid >> 5, lane = tid & 31;

    // ---- LN stats ----
    {
        int lg = l0 + lane;
        bool ok = (lg >= 0 && lg < Ll);
        float s = 0.f, sq = 0.f;
        if (ok) {
            const float* xp = x + (size_t)(b * Cc + w) * Ll + lg;
            for (int c = 0; c < 32; c++) {
                float v = __ldg(xp + (size_t)c * 8 * Ll);
                s += v; sq += v * v;
            }
        }
        red2[w * 32 + lane]       = s;
        red2[256 + w * 32 + lane] = sq;
    }
    __syncthreads();
    if (tid < 32) {
        float s = 0.f, sq = 0.f;
        #pragma unroll
        for (int k = 0; k < 8; k++) { s += red2[k * 32 + tid]; sq += red2[256 + k * 32 + tid]; }
        float mu = s * (1.f / Cc);
        float var = sq * (1.f / Cc) - mu * mu;
        stat[tid]      = mu;
        stat[32 + tid] = rsqrtf(var + EPSV);
    }
    __syncthreads();

    // ---- normalize + fp16 split -> B [32 l][256 c] ----
    for (int i = tid; i < 128 * 32; i += 256) {
        int cp = i >> 5, l = i & 31;
        int c = cp * 2;
        int lg = l0 + l;
        bool ok = (lg >= 0 && lg < Ll);
        float x0 = ok ? __ldg(&x[(size_t)(b * Cc + c) * Ll + lg]) : 0.f;
        float x1 = ok ? __ldg(&x[(size_t)(b * Cc + c + 1) * Ll + lg]) : 0.f;
        float mu = stat[l], rs = stat[32 + l];
        float v0 = (x0 - mu) * rs * __ldg(&gamma[c]) + __ldg(&beta[c]);
        float v1 = (x1 - mu) * rs * __ldg(&gamma[c + 1]) + __ldg(&beta[c + 1]);
        uint32_t lop;
        uint32_t hip = pack_hi2f(v0, v1, &lop);
        uint32_t by = bswz(l, c);
        *(uint32_t*)(sm + K1_B + by)         = hip;
        *(uint32_t*)(sm + K1_B + 16384 + by) = lop;
    }
    __syncthreads();

    // ---- GEMM: M=512, N=32 ----
    const int lr  = lane & 7;
    const int gb0 = (lane >> 3) & 1;
    const int gb1 = lane >> 4;
    uint32_t bBase[2];
    #pragma unroll
    for (int bp = 0; bp < 2; bp++)
        bBase[bp] = smb + K1_B + (uint32_t)((bp * 16 + gb1 * 8 + lr) * 512);

    float acc[4][4][4];
    #pragma unroll
    for (int mi = 0; mi < 4; mi++)
        #pragma unroll
        for (int nt = 0; nt < 4; nt++)
            #pragma unroll
            for (int q = 0; q < 4; q++) acc[mi][nt][q] = 0.f;

    const uint4* AH[4];
    #pragma unroll
    for (int mi = 0; mi < 4; mi++) {
        int mt = w + mi * 8;
        AH[mi] = g_w1f + mt * 32 + lane;
    }

    #pragma unroll 4
    for (int p = 0; p < 16; ++p) {
        uint32_t kx = (uint32_t)(((p * 2 + gb0) ^ lr) << 4);
        uint32_t Bh[8], Bl[8];
        ldsm4(&Bh[0], bBase[0] + kx);
        ldsm4(&Bh[4], bBase[1] + kx);
        ldsm4(&Bl[0], bBase[0] + 16384 + kx);
        ldsm4(&Bl[4], bBase[1] + 16384 + kx);
        #pragma unroll
        for (int mi = 0; mi < 4; mi++) {
            uint4 ah = __ldg(AH[mi] + p * 1024);
            #pragma unroll
            for (int nt = 0; nt < 4; nt++) {
                mma16816(acc[mi][nt], (const uint32_t*)&ah, &Bh[nt * 2]);
                mma16816(acc[mi][nt], (const uint32_t*)&ah, &Bl[nt * 2]);
            }
        }
    }

    // ---- register epilogue: bias + dwconv + gate + pool ----
    float* redm = red2;
    const int j  = lane & 3;
    const int rl = lane >> 2;
    const int srcL = (lane & ~3) | ((j + 3) & 3);
    const int srcR = (lane & ~3) | ((j + 1) & 3);

    #pragma unroll
    for (int pair = 0; pair < 2; ++pair) {
        #pragma unroll
        for (int q = 0; q < 2; ++q) {
            const int m  = (w + pair * 8) * 16 + q * 8 + rl;
            const int m2 = m + Cc;
            const float biA = __ldg(&b1[m]);
            const float biB = __ldg(&b1[m2]);
            float zA0[4], zA1[4], zB0[4], zB1[4];
            #pragma unroll
            for (int nt = 0; nt < 4; nt++) {
                zA0[nt] = acc[pair][nt][q * 2]     + biA;
                zA1[nt] = acc[pair][nt][q * 2 + 1] + biA;
                zB0[nt] = acc[pair + 2][nt][q * 2]     + biB;
                zB1[nt] = acc[pair + 2][nt][q * 2 + 1] + biB;
            }
            float rA1[4], rA0[4], rB1[4], rB0[4];
            #pragma unroll
            for (int nt = 0; nt < 4; nt++) {
                rA1[nt] = __shfl_sync(0xFFFFFFFFu, zA1[nt], srcL);
                rA0[nt] = __shfl_sync(0xFFFFFFFFu, zA0[nt], srcR);
                rB1[nt] = __shfl_sync(0xFFFFFFFFu, zB1[nt], srcL);
                rB0[nt] = __shfl_sync(0xFFFFFFFFu, zB0[nt], srcR);
            }
            const float wa0 = __ldg(&wd[m * 3 + 0]),  wa1 = __ldg(&wd[m * 3 + 1]),
                        wa2 = __ldg(&wd[m * 3 + 2]),  ba  = __ldg(&bd_[m]);
            const float wb0 = __ldg(&wd[m2 * 3 + 0]), wb1 = __ldg(&wd[m2 * 3 + 1]),
                        wb2 = __ldg(&wd[m2 * 3 + 2]), bb  = __ldg(&bd_[m2]);
            __half* orow = g_gate + (size_t)(b * Cc + m) * Ll;
            float psum = 0.f;
            #pragma unroll
            for (int nt = 0; nt < 4; nt++) {
                #pragma unroll
                for (int e = 0; e < 2; e++) {
                    int co = nt * 8 + 2 * j + e;
                    if (co >= 1 && co <= 30) {
                        int lg = l0 + co;
                        if (lg >= 0 && lg < Ll) {
                            float am1, ac, ap1, bm1, bc, bp1;
                            if (e == 0) {
                                am1 = (j == 0) ? (nt > 0 ? rA1[nt - 1] : 0.f) : rA1[nt];
                                bm1 = (j == 0) ? (nt > 0 ? rB1[nt - 1] : 0.f) : rB1[nt];
                                ac = zA0[nt]; ap1 = zA1[nt];
                                bc = zB0[nt]; bp1 = zB1[nt];
                            } else {
                                am1 = zA0[nt]; ac = zA1[nt];
                                bm1 = zB0[nt]; bc = zB1[nt];
                                ap1 = (j == 3) ? (nt < 3 ? rA0[nt + 1] : 0.f) : rA0[nt];
                                bp1 = (j == 3) ? (nt < 3 ? rB0[nt + 1] : 0.f) : rB0[nt];
                            }
                            if (lg - 1 < 0)   { am1 = 0.f; bm1 = 0.f; }
                            if (lg + 1 >= Ll) { ap1 = 0.f; bp1 = 0.f; }
                            float d1 = wa0 * am1 + wa1 * ac + wa2 * ap1 + ba;
                            float d2 = wb0 * bm1 + wb1 * bc + wb2 * bp1 + bb;
                            float g = d1 * d2;
                            orow[lg] = __float2half_rn(g);
                            psum += g;
                        }
                    }
                }
            }
            psum += __shfl_xor_sync(0xFFFFFFFFu, psum, 1);
            psum += __shfl_xor_sync(0xFFFFFFFFu, psum, 2);
            if (j == 0) redm[m] = psum;
        }
    }
    __syncthreads();
    if (tid < 256) {
        float v = redm[tid];
        if (v != 0.f) atomicAdd(&g_pool[b * Cc + tid], v * (1.f / Ll));
    }
}

// ---------------------------------------------------------------------------
// K3: SCA scale = sigmoid(ws @ pool + bs); one warp per output
// ---------------------------------------------------------------------------
__global__ __launch_bounds__(256) void k3_scale(
    const float* __restrict__ ws, const float* __restrict__ bs)
{
    __shared__ float sp[Cc];
    const int b = blockIdx.x;
    const int w = threadIdx.x >> 5, lane = threadIdx.x & 31;
    const int c = blockIdx.y * 8 + w;
    sp[threadIdx.x] = g_pool[b * Cc + threadIdx.x];
    __syncthreads();
    const float4* wr = (const float4*)(ws + c * Cc);
    const float4* pp = (const float4*)sp;
    float4 a0 = __ldg(&wr[lane * 2]), a1 = __ldg(&wr[lane * 2 + 1]);
    float4 p0 = pp[lane * 2], p1 = pp[lane * 2 + 1];
    float s = a0.x * p0.x + a0.y * p0.y + a0.z * p0.z + a0.w * p0.w
            + a1.x * p1.x + a1.y * p1.y + a1.z * p1.z + a1.w * p1.w;
    #pragma unroll
    for (int o = 16; o; o >>= 1) s += __shfl_xor_sync(0xFFFFFFFFu, s, o);
    if (lane == 0)
        g_scale[b * Cc + c] = 1.f / (1.f + expf(-(s + __ldg(&bs[c]))));
}

// ---------------------------------------------------------------------------
// K4: pw2 with scale FOLDED INTO A; B = raw fp16 gate (exact, no lo term).
// M=256, N=64, 16 MMAs/panel/warp. 256 threads, 2 CTAs/SM.
// smem: B [0,32K); sscale [32K,+1K)
// ---------------------------------------------------------------------------
#define K4_B 0
#define K4_SC 32768
#define K4_SMEM 33792

__global__ __launch_bounds__(256, 2) void k4_pw2(
    const float* __restrict__ x, const float* __restrict__ b2,
    float* __restrict__ out)
{
    extern __shared__ char sm[];
    float* ss = (float*)(sm + K4_SC);
    const uint32_t smb = smem_u32(sm);
    const int b = blockIdx.y, tile = blockIdx.x, tid = threadIdx.x;
    const int w = tid >> 5, lane = tid & 31;
    const int l0 = tile * 64;

    // ---- stage scale; B tile = raw fp16 gate [64 l][256 c] (pure copy) ----
    ss[tid] = __ldg(&g_scale[b * Cc + tid]);
    for (int i = tid; i < 128 * 64; i += 256) {
        int cp = i >> 6, l = i & 63;
        int c = cp * 2;
        __half h0 = g_gate[(size_t)(b * Cc + c) * Ll + l0 + l];
        __half h1 = g_gate[(size_t)(b * Cc + c + 1) * Ll + l0 + l];
        __half2 hp = __halves2half2(h0, h1);
        *(uint32_t*)(sm + K4_B + bswz(l, c)) = *reinterpret_cast<uint32_t*>(&hp);
    }
    __syncthreads();

    const int lr  = lane & 7;
    const int gb0 = (lane >> 3) & 1;
    const int gb1 = lane >> 4;
    uint32_t bBase[4];
    #pragma unroll
    for (int bp = 0; bp < 4; bp++)
        bBase[bp] = smb + K4_B + (uint32_t)((bp * 16 + gb1 * 8 + lr) * 512);

    float acc[2][8][4];
    #pragma unroll
    for (int mt = 0; mt < 2; mt++)
        #pragma unroll
        for (int nt = 0; nt < 8; nt++)
            #pragma unroll
            for (int q = 0; q < 4; q++) acc[mt][nt][q] = 0.f;

    const uint4* A0H = g_w2f + w * 32 + lane;          // mt = w
    const uint4* A1H = g_w2f + (8 + w) * 32 + lane;    // mt = 8 + w
    const int c0 = (lane & 3) * 2;                     // k-col within panel

    #pragma unroll 2
    for (int p = 0; p < 16; ++p) {
        uint32_t kx = (uint32_t)(((p * 2 + gb0) ^ lr) << 4);
        uint32_t Bh[16];
        #pragma unroll
        for (int bp = 0; bp < 4; bp++)
            ldsm4(&Bh[bp * 4], bBase[bp] + kx);
        uint4 a0 = __ldg(A0H + p * 512);
        uint4 a1 = __ldg(A1H + p * 512);
        // fold scale into A (k = channel): cols p*16 + c0 (+1) and +8 (+9)
        int cb = p * 16 + c0;
        float s0 = ss[cb],     s1 = ss[cb + 1];
        float s8 = ss[cb + 8], s9 = ss[cb + 9];
        a0.x = h2scale(a0.x, s0, s1);  a0.y = h2scale(a0.y, s0, s1);
        a0.z = h2scale(a0.z, s8, s9);  a0.w = h2scale(a0.w, s8, s9);
        a1.x = h2scale(a1.x, s0, s1);  a1.y = h2scale(a1.y, s0, s1);
        a1.z = h2scale(a1.z, s8, s9);  a1.w = h2scale(a1.w, s8, s9);
        #pragma unroll
        for (int nt = 0; nt < 8; nt++) {
            mma16816(acc[0][nt], (const uint32_t*)&a0, &Bh[nt * 2]);
            mma16816(acc[1][nt], (const uint32_t*)&a1, &Bh[nt * 2]);
        }
    }

    // ---- register epilogue: out = acc + b2 + x (float2 stores, 64 cols) ----
    const int j  = lane & 3;
    const int rl = lane >> 2;
    #pragma unroll
    for (int mt = 0; mt < 2; mt++) {
        const int r0 = (w + mt * 8) * 16 + rl;
        const float bi0 = __ldg(&b2[r0]);
        const float bi1 = __ldg(&b2[r0 + 8]);
        const float* xr0 = x + (size_t)(b * Cc + r0) * Ll + l0;
        const float* xr1 = xr0 + 8 * Ll;
        float* or0 = out + (size_t)(b * Cc + r0) * Ll + l0;
        float* or1 = or0 + 8 * Ll;
        #pragma unroll
        for (int nt = 0; nt < 8; nt++) {
            int co = nt * 8 + 2 * j;
            float2 x0 = *(const float2*)(xr0 + co);
            float2 x1 = *(const float2*)(xr1 + co);
            float2 o0, o1;
            o0.x = acc[mt][nt][0] + bi0 + x0.x;
            o0.y = acc[mt][nt][1] + bi0 + x0.y;
            o1.x = acc[mt][nt][2] + bi1 + x1.x;
            o1.y = acc[mt][nt][3] + bi1 + x1.y;
            *(float2*)(or0 + co) = o0;
            *(float2*)(or1 + co) = o1;
        }
    }
}

// ---------------------------------------------------------------------------
extern "C" void kernel_launch(void* const* d_in, const int* in_sizes, int n_in,
                              void* d_out, int out_size)
{
    const float* x     = (const float*)d_in[0];
    const float* gamma = (const float*)d_in[1];
    const float* beta  = (const float*)d_in[2];
    const float* w1    = (const float*)d_in[3];
    const float* b1    = (const float*)d_in[4];
    const float* wd    = (const float*)d_in[5];
    const float* bd    = (const float*)d_in[6];
    const float* wsm   = (const float*)d_in[7];
    const float* bs    = (const float*)d_in[8];
    const float* w2    = (const float*)d_in[9];
    const float* b2    = (const float*)d_in[10];
    float* out = (float*)d_out;

    k0_split<<<96, 256>>>(w1, w2);
    dim3 g1(NT1, Bb);
    k1_ln_pw1<<<g1, 256, K1_SMEM>>>(x, gamma, beta, b1, wd, bd);
    dim3 g3(Bb, 32);
    k3_scale<<<g3, 256>>>(wsm, bs);
    dim3 g4(Ll / 64, Bb);
    k4_pw2<<<g4, 256, K4_SMEM>>>(x, b2, out);
}